// round 1
// baseline (speedup 1.0000x reference)
#include <cuda_runtime.h>
#include <cuda_bf16.h>

#define N_NODES  100000
#define N_EDGES  600000
#define N_GRAPHS 2000
#define HID      128
#define LAYERS   6
#define SS       132   // smem row stride (floats), 132%4==0 for float4, breaks bank alignment

// Persistent scratch (allocation-free): node features and aggregate buffer.
__device__ float g_x  [(size_t)N_NODES * HID];
__device__ float g_agg[(size_t)N_NODES * HID];

// ---------------------------------------------------------------------------
// Embedding lookup: x[i] = emb[tok[i]]; also primes g_agg = x (GIN: h = x + sum)
// ---------------------------------------------------------------------------
__global__ void embed_kernel(const int* __restrict__ tok,
                             const float* __restrict__ emb) {
    int i = blockIdx.x * blockDim.x + threadIdx.x;     // float4 index
    if (i >= N_NODES * 32) return;
    int node = i >> 5;
    int d    = i & 31;
    int t    = tok[node];
    float4 v = ((const float4*)emb)[t * 32 + d];
    ((float4*)g_x)[i]   = v;
    ((float4*)g_agg)[i] = v;
}

// ---------------------------------------------------------------------------
// Edge scatter: one warp per edge; agg[dst] += x[src] via float4 atomics.
// ---------------------------------------------------------------------------
__global__ void scatter_kernel(const int* __restrict__ ei) {
    int w    = (blockIdx.x * blockDim.x + threadIdx.x) >> 5;
    int lane = threadIdx.x & 31;
    if (w >= N_EDGES) return;
    int src = __ldg(ei + w);
    int dst = __ldg(ei + N_EDGES + w);
    float4 v = ((const float4*)g_x)[src * 32 + lane];
    atomicAdd(((float4*)g_agg) + dst * 32 + lane, v);   // sm_90+: RED.128
}

// ---------------------------------------------------------------------------
// Load W (128x128 row-major [k][c]) transposed into smem as sW[c*SS + k].
// Global reads are strided (kb fast) -> extra L2 sectors, but W is tiny;
// smem stores are STS.128 at full crossbar bandwidth.
// ---------------------------------------------------------------------------
__device__ __forceinline__ void loadWT(float* __restrict__ sW,
                                       const float* __restrict__ Wg, int tid) {
    const float4* W4 = (const float4*)Wg;
#pragma unroll
    for (int t = tid; t < 1024; t += 256) {
        int kb = t & 31;       // k-block of 4
        int cb = t >> 5;       // col-block of 4
        float4 r0 = W4[(kb * 4 + 0) * 32 + cb];
        float4 r1 = W4[(kb * 4 + 1) * 32 + cb];
        float4 r2 = W4[(kb * 4 + 2) * 32 + cb];
        float4 r3 = W4[(kb * 4 + 3) * 32 + cb];
        *(float4*)&sW[(cb * 4 + 0) * SS + kb * 4] = make_float4(r0.x, r1.x, r2.x, r3.x);
        *(float4*)&sW[(cb * 4 + 1) * SS + kb * 4] = make_float4(r0.y, r1.y, r2.y, r3.y);
        *(float4*)&sW[(cb * 4 + 2) * SS + kb * 4] = make_float4(r0.z, r1.z, r2.z, r3.z);
        *(float4*)&sW[(cb * 4 + 3) * SS + kb * 4] = make_float4(r0.w, r1.w, r2.w, r3.w);
    }
}

// 128x128x128 register-tiled GEMM fragment: acc[i][j] = sum_k sA[r_i][k]*sW[c_j][k]
// rows r_i = row_base + 8i  (stride-8 -> 8 distinct bank quads on a-loads)
// cols c_j = col_base + 4j  (lane_c gives 4 quads, broadcast over lane_r)
__device__ __forceinline__ void gemm_tile(const float* __restrict__ sA,
                                          const float* __restrict__ sW,
                                          int row_base, int col_base,
                                          float (&acc)[8][8]) {
#pragma unroll
    for (int i = 0; i < 8; i++)
#pragma unroll
        for (int j = 0; j < 8; j++) acc[i][j] = 0.f;

    for (int k4 = 0; k4 < 32; k4++) {
        int k = k4 * 4;
        float4 a[8], b[8];
#pragma unroll
        for (int i = 0; i < 8; i++)
            a[i] = *(const float4*)&sA[(row_base + 8 * i) * SS + k];
#pragma unroll
        for (int j = 0; j < 8; j++)
            b[j] = *(const float4*)&sW[(col_base + 4 * j) * SS + k];
#pragma unroll
        for (int i = 0; i < 8; i++)
#pragma unroll
            for (int j = 0; j < 8; j++) {
                acc[i][j] = fmaf(a[i].x, b[j].x, acc[i][j]);
                acc[i][j] = fmaf(a[i].y, b[j].y, acc[i][j]);
                acc[i][j] = fmaf(a[i].z, b[j].z, acc[i][j]);
                acc[i][j] = fmaf(a[i].w, b[j].w, acc[i][j]);
            }
    }
}

// ---------------------------------------------------------------------------
// Fused GIN MLP for one layer: x_new = relu( relu((x+agg)@W1+b1) @ W2 + b2 )
// One block = 128 nodes. Writes x_new to g_x (and g_agg for next layer).
// ---------------------------------------------------------------------------
__global__ __launch_bounds__(256, 1) void mlp_kernel(
    const float* __restrict__ W1, const float* __restrict__ b1,
    const float* __restrict__ W2, const float* __restrict__ b2,
    int write_agg)
{
    extern __shared__ float sm[];
    float* sA = sm;                 // 128 x SS : input tile / h tile
    float* sW = sm + 128 * SS;      // 128 x SS : transposed weights [c][k]

    int tid   = threadIdx.x;
    int node0 = blockIdx.x * 128;

    // load A tile (x + agg lives in g_agg)
#pragma unroll
    for (int f = tid; f < 4096; f += 256) {
        int row = f >> 5, k4 = f & 31;
        int gr = node0 + row;
        float4 v = make_float4(0.f, 0.f, 0.f, 0.f);
        if (gr < N_NODES) v = ((const float4*)g_agg)[gr * 32 + k4];
        *(float4*)&sA[row * SS + k4 * 4] = v;
    }
    loadWT(sW, W1, tid);
    __syncthreads();

    int warp = tid >> 5, lane = tid & 31;
    int row_base = (warp >> 2) * 64 + (lane >> 2);   // + 8i
    int col_base = (warp & 3) * 32 + (lane & 3);     // + 4j

    float acc[8][8];
    gemm_tile(sA, sW, row_base, col_base, acc);
    __syncthreads();

    // h = relu(acc + b1) -> sA  (scalar stores hit 32 distinct banks)
#pragma unroll
    for (int j = 0; j < 8; j++) {
        float bj = __ldg(b1 + col_base + 4 * j);
#pragma unroll
        for (int i = 0; i < 8; i++) {
            float v = acc[i][j] + bj;
            sA[(row_base + 8 * i) * SS + (col_base + 4 * j)] = fmaxf(v, 0.f);
        }
    }
    loadWT(sW, W2, tid);
    __syncthreads();

    gemm_tile(sA, sW, row_base, col_base, acc);
    __syncthreads();

#pragma unroll
    for (int j = 0; j < 8; j++) {
        float bj = __ldg(b2 + col_base + 4 * j);
#pragma unroll
        for (int i = 0; i < 8; i++) {
            float v = acc[i][j] + bj;
            sA[(row_base + 8 * i) * SS + (col_base + 4 * j)] = fmaxf(v, 0.f);
        }
    }
    __syncthreads();

    // vectorized writeback: x (and agg baseline for next layer)
#pragma unroll
    for (int f = tid; f < 4096; f += 256) {
        int row = f >> 5, k4 = f & 31;
        int gr = node0 + row;
        if (gr < N_NODES) {
            float4 v = *(float4*)&sA[row * SS + k4 * 4];
            ((float4*)g_x)[gr * 32 + k4] = v;
            if (write_agg) ((float4*)g_agg)[gr * 32 + k4] = v;
        }
    }
}

// ---------------------------------------------------------------------------
// Global mean pool. batch[] is sorted -> binary-search per-graph node range.
// ---------------------------------------------------------------------------
__global__ void pool_kernel(const int* __restrict__ batch,
                            float* __restrict__ out) {
    int g = blockIdx.x;
    __shared__ int s_range[2];
    if (threadIdx.x == 0) {
        int lo = 0, hi = N_NODES;
        while (lo < hi) { int m = (lo + hi) >> 1; if (batch[m] < g) lo = m + 1; else hi = m; }
        s_range[0] = lo;
        lo = 0; hi = N_NODES;
        while (lo < hi) { int m = (lo + hi) >> 1; if (batch[m] < g + 1) lo = m + 1; else hi = m; }
        s_range[1] = lo;
    }
    __syncthreads();
    int start = s_range[0], end = s_range[1];
    float sum = 0.f;
    for (int n = start; n < end; n++)
        sum += g_x[(size_t)n * HID + threadIdx.x];
    float cnt = (float)(end - start);
    out[g * HID + threadIdx.x] = sum / fmaxf(cnt, 1.0f);
}

// ---------------------------------------------------------------------------
// Inputs (metadata order): x_tokens, edge_index, batch, emb, W1, b1, W2, b2
// ---------------------------------------------------------------------------
extern "C" void kernel_launch(void* const* d_in, const int* in_sizes, int n_in,
                              void* d_out, int out_size) {
    const int*   tok   = (const int*)  d_in[0];
    const int*   ei    = (const int*)  d_in[1];
    const int*   batch = (const int*)  d_in[2];
    const float* emb   = (const float*)d_in[3];
    const float* W1    = (const float*)d_in[4];
    const float* b1    = (const float*)d_in[5];
    const float* W2    = (const float*)d_in[6];
    const float* b2    = (const float*)d_in[7];
    float* out = (float*)d_out;

    const size_t smem = (size_t)2 * 128 * SS * sizeof(float);   // 135168 B
    cudaFuncSetAttribute(mlp_kernel, cudaFuncAttributeMaxDynamicSharedMemorySize,
                         (int)smem);

    embed_kernel<<<(N_NODES * 32 + 255) / 256, 256>>>(tok, emb);

    for (int l = 0; l < LAYERS; l++) {
        scatter_kernel<<<(N_EDGES * 32 + 255) / 256, 256>>>(ei);
        mlp_kernel<<<(N_NODES + 127) / 128, 256, smem>>>(
            W1 + (size_t)l * HID * HID, b1 + (size_t)l * HID,
            W2 + (size_t)l * HID * HID, b2 + (size_t)l * HID,
            (l < LAYERS - 1) ? 1 : 0);
    }

    pool_kernel<<<N_GRAPHS, HID>>>(batch, out);
}

// round 4
// speedup vs baseline: 1.5282x; 1.5282x over previous
#include <cuda_runtime.h>
#include <cuda_bf16.h>
#include <cstdint>

#define N_NODES  100000
#define N_EDGES  600000
#define N_GRAPHS 2000
#define HID      128
#define LAYERS   6
#define SA       136      // bf16 row stride for smem tiles (16B-multiple, conflict-free ldmatrix)

// ---------------------------------------------------------------------------
// Persistent scratch (allocation-free)
// ---------------------------------------------------------------------------
__device__ float g_x  [(size_t)N_NODES * HID];
__device__ float g_agg[(size_t)N_NODES * HID];
// Pre-split, transposed, padded weight images: [hilo(2)][which(2)*L+l][c][k pad SA]
__device__ __align__(16) __nv_bfloat16 g_wt[(size_t)2 * 2 * LAYERS * HID * SA];

// ---------------------------------------------------------------------------
// Embedding lookup; primes g_agg = x
// ---------------------------------------------------------------------------
__global__ void embed_kernel(const int* __restrict__ tok,
                             const float* __restrict__ emb) {
    int i = blockIdx.x * blockDim.x + threadIdx.x;
    if (i >= N_NODES * 32) return;
    int node = i >> 5, d = i & 31;
    int t = tok[node];
    float4 v = ((const float4*)emb)[t * 32 + d];
    ((float4*)g_x)[i]   = v;
    ((float4*)g_agg)[i] = v;
}

// ---------------------------------------------------------------------------
// Edge scatter: one warp per edge; agg[dst] += x[src] via float4 atomics.
// ---------------------------------------------------------------------------
__global__ void scatter_kernel(const int* __restrict__ ei) {
    int w = (blockIdx.x * blockDim.x + threadIdx.x) >> 5;
    int lane = threadIdx.x & 31;
    if (w >= N_EDGES) return;
    int src = __ldg(ei + w);
    int dst = __ldg(ei + N_EDGES + w);
    float4 v = ((const float4*)g_x)[src * 32 + lane];
    atomicAdd(((float4*)g_agg) + dst * 32 + lane, v);
}

// ---------------------------------------------------------------------------
// Weight prep: split W[k][c] into bf16 hi/lo, store transposed Wt[c][k]
// with row stride SA into global images (block copies are straight float4).
// ---------------------------------------------------------------------------
__global__ void prep_w(const float* __restrict__ W1, const float* __restrict__ W2) {
    int i = blockIdx.x * blockDim.x + threadIdx.x;
    if (i >= 2 * LAYERS * HID * HID) return;
    int which = i / (LAYERS * HID * HID);
    int r = i % (LAYERS * HID * HID);
    int l = r / (HID * HID);
    int kc = r % (HID * HID);
    int k = kc / HID, c = kc % HID;
    const float* W = which ? W2 : W1;
    float v = W[(size_t)l * HID * HID + k * HID + c];
    __nv_bfloat16 hi = __float2bfloat16(v);
    __nv_bfloat16 lo = __float2bfloat16(v - __bfloat162float(hi));
    size_t img = (size_t)which * LAYERS + l;
    size_t o = img * HID * SA + (size_t)c * SA + k;
    g_wt[o] = hi;
    g_wt[(size_t)2 * LAYERS * HID * SA + o] = lo;
}

// ---------------------------------------------------------------------------
// mma.sync helpers
// ---------------------------------------------------------------------------
__device__ __forceinline__ uint32_t smem_u32(const void* p) {
    uint32_t a;
    asm("{ .reg .u64 t; cvta.to.shared.u64 t, %1; cvt.u32.u64 %0, t; }"
        : "=r"(a) : "l"(p));
    return a;
}
__device__ __forceinline__ void ldm_x4(uint32_t (&r)[4], uint32_t addr) {
    asm volatile("ldmatrix.sync.aligned.m8n8.x4.shared.b16 {%0,%1,%2,%3}, [%4];"
                 : "=r"(r[0]), "=r"(r[1]), "=r"(r[2]), "=r"(r[3]) : "r"(addr));
}
__device__ __forceinline__ void mma16816(float (&d)[4], const uint32_t (&a)[4],
                                         uint32_t b0, uint32_t b1) {
    asm volatile(
        "mma.sync.aligned.m16n8k16.row.col.f32.bf16.bf16.f32 "
        "{%0,%1,%2,%3}, {%4,%5,%6,%7}, {%8,%9}, {%0,%1,%2,%3};"
        : "+f"(d[0]), "+f"(d[1]), "+f"(d[2]), "+f"(d[3])
        : "r"(a[0]), "r"(a[1]), "r"(a[2]), "r"(a[3]), "r"(b0), "r"(b1));
}
__device__ __forceinline__ uint32_t pk(__nv_bfloat16 a, __nv_bfloat16 b) {
    return (uint32_t)__bfloat16_as_ushort(a) |
           ((uint32_t)__bfloat16_as_ushort(b) << 16);
}

// ---------------------------------------------------------------------------
// Fused GIN MLP: x_new = relu( relu((x+agg)@W1+b1) @ W2 + b2 )
// Block = 128 nodes, 256 threads (8 warps, warp tile 32x64).
// A(hi/lo) + W1(hi/lo) + W2(hi/lo) all resident in smem.
// ---------------------------------------------------------------------------
#define TILE_B  (HID * SA * 2)            // 34816 bytes per 128x128 bf16 tile
#define SMEM_BYTES (6 * TILE_B)           // 208896

// 3-product split GEMM over one warp tile: acc += Ahi*Bhi + Ahi*Blo + Alo*Bhi
__device__ __forceinline__ void gemm_warp(
    uint32_t aAhi, uint32_t aAlo, uint32_t aWh, uint32_t aWl,
    int m0, int n0, int arow_off, int akoff, int brow_off, int bkoff,
    float (&acc)[2][8][4])
{
#pragma unroll
    for (int kb = 0; kb < HID; kb += 16) {
        uint32_t ah[2][4], al[2][4], bh[4][4], bl[4][4];
#pragma unroll
        for (int s = 0; s < 2; s++) {
            uint32_t ro = (uint32_t)((m0 + s * 16 + arow_off) * SA + kb + akoff) * 2;
            ldm_x4(ah[s], aAhi + ro);
            ldm_x4(al[s], aAlo + ro);
        }
#pragma unroll
        for (int nb = 0; nb < 4; nb++) {
            uint32_t ro = (uint32_t)((n0 + nb * 16 + brow_off) * SA + kb + bkoff) * 2;
            ldm_x4(bh[nb], aWh + ro);
            ldm_x4(bl[nb], aWl + ro);
        }
#pragma unroll
        for (int s = 0; s < 2; s++)
#pragma unroll
            for (int j = 0; j < 8; j++) {
                int nb = j >> 1, h = (j & 1) * 2;
                mma16816(acc[s][j], ah[s], bh[nb][h], bh[nb][h + 1]);
                mma16816(acc[s][j], ah[s], bl[nb][h], bl[nb][h + 1]);
                mma16816(acc[s][j], al[s], bh[nb][h], bh[nb][h + 1]);
            }
    }
}

__global__ void __launch_bounds__(256, 1) mlp_mma(
    const float* __restrict__ b1, const float* __restrict__ b2, int l,
    int write_agg)
{
    extern __shared__ __align__(16) char S[];
    char* pAhi = S;
    char* pAlo = S + TILE_B;
    char* pW1h = S + 2 * TILE_B;
    char* pW1l = S + 3 * TILE_B;
    char* pW2h = S + 4 * TILE_B;
    char* pW2l = S + 5 * TILE_B;
    uint32_t aAhi = smem_u32(pAhi);
    uint32_t aAlo = aAhi + TILE_B;
    uint32_t aW1h = aAhi + 2 * TILE_B, aW1l = aAhi + 3 * TILE_B;
    uint32_t aW2h = aAhi + 4 * TILE_B, aW2l = aAhi + 5 * TILE_B;

    int tid = threadIdx.x, warp = tid >> 5, lane = tid & 31;
    int node0 = blockIdx.x * 128;

    // ---- load A (x+agg), split hi/lo ----
    const float4* agg4 = (const float4*)g_agg;
#pragma unroll 4
    for (int it = 0; it < 16; it++) {
        int idx = tid + it * 256;
        int row = idx >> 5, k4 = idx & 31;
        int gr = node0 + row;
        float4 v = make_float4(0.f, 0.f, 0.f, 0.f);
        if (gr < N_NODES) v = agg4[(size_t)gr * 32 + k4];
        __nv_bfloat16 h0 = __float2bfloat16(v.x), h1 = __float2bfloat16(v.y);
        __nv_bfloat16 h2 = __float2bfloat16(v.z), h3 = __float2bfloat16(v.w);
        __nv_bfloat16 l0 = __float2bfloat16(v.x - __bfloat162float(h0));
        __nv_bfloat16 l1 = __float2bfloat16(v.y - __bfloat162float(h1));
        __nv_bfloat16 l2 = __float2bfloat16(v.z - __bfloat162float(h2));
        __nv_bfloat16 l3 = __float2bfloat16(v.w - __bfloat162float(h3));
        size_t off = ((size_t)row * SA + k4 * 4) * 2;
        *(uint2*)(pAhi + off) = make_uint2(pk(h0, h1), pk(h2, h3));
        *(uint2*)(pAlo + off) = make_uint2(pk(l0, l1), pk(l2, l3));
    }

    // ---- copy weight images (hi/lo for both GEMMs) ----
    {
        const size_t istr = (size_t)HID * SA;              // elems per image
        const size_t lstr = (size_t)2 * LAYERS * HID * SA; // hi->lo offset
        const float4* s1h = (const float4*)(g_wt + (size_t)l * istr);
        const float4* s1l = (const float4*)(g_wt + lstr + (size_t)l * istr);
        const float4* s2h = (const float4*)(g_wt + (size_t)(LAYERS + l) * istr);
        const float4* s2l = (const float4*)(g_wt + lstr + (size_t)(LAYERS + l) * istr);
        float4* d1h = (float4*)pW1h; float4* d1l = (float4*)pW1l;
        float4* d2h = (float4*)pW2h; float4* d2l = (float4*)pW2l;
#pragma unroll 2
        for (int i = tid; i < TILE_B / 16; i += 256) {
            d1h[i] = s1h[i]; d1l[i] = s1l[i];
            d2h[i] = s2h[i]; d2l[i] = s2l[i];
        }
    }
    __syncthreads();

    // warp tiling: 8 warps -> (4 m) x (2 n); warp tile 32x64
    int m0 = (warp >> 1) * 32;
    int n0 = (warp & 1) * 64;
    int g = lane >> 3;
    int arow_off = (lane & 7) + ((g & 1) << 3);
    int akoff    = (g >> 1) << 3;
    int brow_off = (lane & 7) + ((g >> 1) << 3);
    int bkoff    = (g & 1) << 3;

    float acc[2][8][4];
#pragma unroll
    for (int s = 0; s < 2; s++)
#pragma unroll
        for (int j = 0; j < 8; j++)
#pragma unroll
            for (int c = 0; c < 4; c++) acc[s][j][c] = 0.f;

    // ---- GEMM 1 ----
    gemm_warp(aAhi, aAlo, aW1h, aW1l, m0, n0, arow_off, akoff, brow_off, bkoff, acc);

    // ---- epilogue 1: h = relu(acc + b1), split hi/lo back into A tiles ----
    {
        int r0 = m0 + (lane >> 2);
#pragma unroll
        for (int j = 0; j < 8; j++) {
            int col = n0 + j * 8 + (lane & 3) * 2;
            float bj0 = __ldg(b1 + col), bj1 = __ldg(b1 + col + 1);
#pragma unroll
            for (int s = 0; s < 2; s++) {
                int rA = r0 + s * 16, rB = rA + 8;
                float v0 = fmaxf(acc[s][j][0] + bj0, 0.f);
                float v1 = fmaxf(acc[s][j][1] + bj1, 0.f);
                float v2 = fmaxf(acc[s][j][2] + bj0, 0.f);
                float v3 = fmaxf(acc[s][j][3] + bj1, 0.f);
                __nv_bfloat16 h0 = __float2bfloat16(v0), h1 = __float2bfloat16(v1);
                __nv_bfloat16 h2 = __float2bfloat16(v2), h3 = __float2bfloat16(v3);
                __nv_bfloat16 q0 = __float2bfloat16(v0 - __bfloat162float(h0));
                __nv_bfloat16 q1 = __float2bfloat16(v1 - __bfloat162float(h1));
                __nv_bfloat16 q2 = __float2bfloat16(v2 - __bfloat162float(h2));
                __nv_bfloat16 q3 = __float2bfloat16(v3 - __bfloat162float(h3));
                size_t oA = ((size_t)rA * SA + col) * 2;
                size_t oB = ((size_t)rB * SA + col) * 2;
                *(uint32_t*)(pAhi + oA) = pk(h0, h1);
                *(uint32_t*)(pAlo + oA) = pk(q0, q1);
                *(uint32_t*)(pAhi + oB) = pk(h2, h3);
                *(uint32_t*)(pAlo + oB) = pk(q2, q3);
            }
        }
    }
    // Warp pair (same m0, other n0) wrote the other 64 H-columns of our rows:
    // GEMM 2 reads all 128 k-columns -> block-wide barrier required.
    __syncthreads();

#pragma unroll
    for (int s = 0; s < 2; s++)
#pragma unroll
        for (int j = 0; j < 8; j++)
#pragma unroll
            for (int c = 0; c < 4; c++) acc[s][j][c] = 0.f;

    // ---- GEMM 2 (W2 already resident) ----
    gemm_warp(aAhi, aAlo, aW2h, aW2l, m0, n0, arow_off, akoff, brow_off, bkoff, acc);
    // stage reuses the A region; pair warp may still be reading A -> barrier.
    __syncthreads();

    // ---- epilogue 2: relu(acc + b2) -> fp32 stage (reuses A region) ----
    float* stage = (float*)S;    // 128 x 132 fp32 = 67584 B <= 2*TILE_B
    {
        int r0 = m0 + (lane >> 2);
#pragma unroll
        for (int j = 0; j < 8; j++) {
            int col = n0 + j * 8 + (lane & 3) * 2;
            float bj0 = __ldg(b2 + col), bj1 = __ldg(b2 + col + 1);
#pragma unroll
            for (int s = 0; s < 2; s++) {
                int rA = r0 + s * 16, rB = rA + 8;
                stage[rA * 132 + col]     = fmaxf(acc[s][j][0] + bj0, 0.f);
                stage[rA * 132 + col + 1] = fmaxf(acc[s][j][1] + bj1, 0.f);
                stage[rB * 132 + col]     = fmaxf(acc[s][j][2] + bj0, 0.f);
                stage[rB * 132 + col + 1] = fmaxf(acc[s][j][3] + bj1, 0.f);
            }
        }
    }
    __syncthreads();

    // ---- coalesced writeback ----
    float4* x4 = (float4*)g_x;
    float4* a4 = (float4*)g_agg;
#pragma unroll 4
    for (int it = 0; it < 16; it++) {
        int idx = tid + it * 256;
        int row = idx >> 5, k4 = idx & 31;
        int gr = node0 + row;
        if (gr < N_NODES) {
            float4 v = *(float4*)&stage[row * 132 + k4 * 4];
            x4[(size_t)gr * 32 + k4] = v;
            if (write_agg) a4[(size_t)gr * 32 + k4] = v;
        }
    }
}

// ---------------------------------------------------------------------------
// Global mean pool (batch sorted -> binary-search ranges)
// ---------------------------------------------------------------------------
__global__ void pool_kernel(const int* __restrict__ batch,
                            float* __restrict__ out) {
    int g = blockIdx.x;
    __shared__ int s_range[2];
    if (threadIdx.x == 0) {
        int lo = 0, hi = N_NODES;
        while (lo < hi) { int m = (lo + hi) >> 1; if (batch[m] < g) lo = m + 1; else hi = m; }
        s_range[0] = lo;
        lo = 0; hi = N_NODES;
        while (lo < hi) { int m = (lo + hi) >> 1; if (batch[m] < g + 1) lo = m + 1; else hi = m; }
        s_range[1] = lo;
    }
    __syncthreads();
    int start = s_range[0], end = s_range[1];
    float sum = 0.f;
    for (int n = start; n < end; n++)
        sum += g_x[(size_t)n * HID + threadIdx.x];
    float cnt = (float)(end - start);
    out[g * HID + threadIdx.x] = sum / fmaxf(cnt, 1.0f);
}

// ---------------------------------------------------------------------------
// Inputs: x_tokens, edge_index, batch, emb, W1, b1, W2, b2
// ---------------------------------------------------------------------------
extern "C" void kernel_launch(void* const* d_in, const int* in_sizes, int n_in,
                              void* d_out, int out_size) {
    const int*   tok   = (const int*)  d_in[0];
    const int*   ei    = (const int*)  d_in[1];
    const int*   batch = (const int*)  d_in[2];
    const float* emb   = (const float*)d_in[3];
    const float* W1    = (const float*)d_in[4];
    const float* b1    = (const float*)d_in[5];
    const float* W2    = (const float*)d_in[6];
    const float* b2    = (const float*)d_in[7];
    float* out = (float*)d_out;

    cudaFuncSetAttribute(mlp_mma, cudaFuncAttributeMaxDynamicSharedMemorySize,
                         SMEM_BYTES);

    prep_w<<<(2 * LAYERS * HID * HID + 255) / 256, 256>>>(W1, W2);
    embed_kernel<<<(N_NODES * 32 + 255) / 256, 256>>>(tok, emb);

    for (int l = 0; l < LAYERS; l++) {
        scatter_kernel<<<(N_EDGES * 32 + 255) / 256, 256>>>(ei);
        mlp_mma<<<(N_NODES + 127) / 128, 256, SMEM_BYTES>>>(
            b1 + (size_t)l * HID, b2 + (size_t)l * HID, l,
            (l < LAYERS - 1) ? 1 : 0);
    }

    pool_kernel<<<N_GRAPHS, HID>>>(batch, out);
}

// round 5
// speedup vs baseline: 1.6179x; 1.0587x over previous
#include <cuda_runtime.h>
#include <cuda_bf16.h>
#include <cstdint>

#define N_NODES  100000
#define N_EDGES  600000
#define N_GRAPHS 2000
#define HID      128
#define LAYERS   6
#define SA       136      // bf16 row stride for smem tiles (16B-multiple, conflict-free ldmatrix)
#define NODES_PB 256      // nodes per block

// ---------------------------------------------------------------------------
// Persistent scratch (allocation-free)
// ---------------------------------------------------------------------------
__device__ float g_x  [(size_t)N_NODES * HID];
__device__ float g_agg[(size_t)N_NODES * HID];
// Pre-split, transposed, padded weight images: [hilo(2)][which(2)*L+l][c][k pad SA]
__device__ __align__(16) __nv_bfloat16 g_wt[(size_t)2 * 2 * LAYERS * HID * SA];

// ---------------------------------------------------------------------------
// Embedding lookup; primes g_agg = x
// ---------------------------------------------------------------------------
__global__ void embed_kernel(const int* __restrict__ tok,
                             const float* __restrict__ emb) {
    int i = blockIdx.x * blockDim.x + threadIdx.x;
    if (i >= N_NODES * 32) return;
    int node = i >> 5, d = i & 31;
    int t = tok[node];
    float4 v = ((const float4*)emb)[t * 32 + d];
    ((float4*)g_x)[i]   = v;
    ((float4*)g_agg)[i] = v;
}

// ---------------------------------------------------------------------------
// Edge scatter: one warp per edge; agg[dst] += x[src] via float4 atomics.
// ---------------------------------------------------------------------------
__global__ void scatter_kernel(const int* __restrict__ ei) {
    int w = (blockIdx.x * blockDim.x + threadIdx.x) >> 5;
    int lane = threadIdx.x & 31;
    if (w >= N_EDGES) return;
    int src = __ldg(ei + w);
    int dst = __ldg(ei + N_EDGES + w);
    float4 v = ((const float4*)g_x)[src * 32 + lane];
    atomicAdd(((float4*)g_agg) + dst * 32 + lane, v);
}

// ---------------------------------------------------------------------------
// Weight prep: split W[k][c] into bf16 hi/lo, store transposed Wt[c][k].
// ---------------------------------------------------------------------------
__global__ void prep_w(const float* __restrict__ W1, const float* __restrict__ W2) {
    int i = blockIdx.x * blockDim.x + threadIdx.x;
    if (i >= 2 * LAYERS * HID * HID) return;
    int which = i / (LAYERS * HID * HID);
    int r = i % (LAYERS * HID * HID);
    int l = r / (HID * HID);
    int kc = r % (HID * HID);
    int k = kc / HID, c = kc % HID;
    const float* W = which ? W2 : W1;
    float v = W[(size_t)l * HID * HID + k * HID + c];
    __nv_bfloat16 hi = __float2bfloat16(v);
    __nv_bfloat16 lo = __float2bfloat16(v - __bfloat162float(hi));
    size_t img = (size_t)which * LAYERS + l;
    size_t o = img * HID * SA + (size_t)c * SA + k;
    g_wt[o] = hi;
    g_wt[(size_t)2 * LAYERS * HID * SA + o] = lo;
}

// ---------------------------------------------------------------------------
// mma.sync helpers
// ---------------------------------------------------------------------------
__device__ __forceinline__ uint32_t smem_u32(const void* p) {
    uint32_t a;
    asm("{ .reg .u64 t; cvta.to.shared.u64 t, %1; cvt.u32.u64 %0, t; }"
        : "=r"(a) : "l"(p));
    return a;
}
__device__ __forceinline__ void ldm_x4(uint32_t (&r)[4], uint32_t addr) {
    asm volatile("ldmatrix.sync.aligned.m8n8.x4.shared.b16 {%0,%1,%2,%3}, [%4];"
                 : "=r"(r[0]), "=r"(r[1]), "=r"(r[2]), "=r"(r[3]) : "r"(addr));
}
__device__ __forceinline__ void mma16816(float (&d)[4], const uint32_t (&a)[4],
                                         uint32_t b0, uint32_t b1) {
    asm volatile(
        "mma.sync.aligned.m16n8k16.row.col.f32.bf16.bf16.f32 "
        "{%0,%1,%2,%3}, {%4,%5,%6,%7}, {%8,%9}, {%0,%1,%2,%3};"
        : "+f"(d[0]), "+f"(d[1]), "+f"(d[2]), "+f"(d[3])
        : "r"(a[0]), "r"(a[1]), "r"(a[2]), "r"(a[3]), "r"(b0), "r"(b1));
}
__device__ __forceinline__ uint32_t pk(__nv_bfloat16 a, __nv_bfloat16 b) {
    return (uint32_t)__bfloat16_as_ushort(a) |
           ((uint32_t)__bfloat16_as_ushort(b) << 16);
}

// ---------------------------------------------------------------------------
// Fused GIN MLP: x_new = relu( relu((x+agg)@W1+b1) @ W2 + b2 )
// Block = 256 nodes, 512 threads (16 warps, warp tile 32x64).
// A(hi/lo, 256 rows) resident; W1 then W2 staged in one hi/lo slot.
// ---------------------------------------------------------------------------
#define WTILE_B  (HID * SA * 2)                 // 34816 B  (128x128 bf16 tile)
#define ATILE_B  (NODES_PB * SA * 2)            // 69632 B  (256 rows)
#define SMEM_BYTES (2 * ATILE_B + 2 * WTILE_B)  // 208896

// 3-product split GEMM, register-lean: only one nb's B-frags live at a time.
__device__ __forceinline__ void gemm_warp(
    uint32_t aAhi, uint32_t aAlo, uint32_t aWh, uint32_t aWl,
    int m0, int n0, int arow_off, int akoff, int brow_off, int bkoff,
    float (&acc)[2][8][4])
{
#pragma unroll
    for (int kb = 0; kb < HID; kb += 16) {
        uint32_t ah[2][4], al[2][4];
#pragma unroll
        for (int s = 0; s < 2; s++) {
            uint32_t ro = (uint32_t)((m0 + s * 16 + arow_off) * SA + kb + akoff) * 2;
            ldm_x4(ah[s], aAhi + ro);
            ldm_x4(al[s], aAlo + ro);
        }
#pragma unroll
        for (int nb = 0; nb < 4; nb++) {
            uint32_t bh[4], bl[4];
            uint32_t ro = (uint32_t)((n0 + nb * 16 + brow_off) * SA + kb + bkoff) * 2;
            ldm_x4(bh, aWh + ro);
            ldm_x4(bl, aWl + ro);
#pragma unroll
            for (int s = 0; s < 2; s++) {
                mma16816(acc[s][2 * nb],     ah[s], bh[0], bh[1]);
                mma16816(acc[s][2 * nb],     ah[s], bl[0], bl[1]);
                mma16816(acc[s][2 * nb],     al[s], bh[0], bh[1]);
                mma16816(acc[s][2 * nb + 1], ah[s], bh[2], bh[3]);
                mma16816(acc[s][2 * nb + 1], ah[s], bl[2], bl[3]);
                mma16816(acc[s][2 * nb + 1], al[s], bh[2], bh[3]);
            }
        }
    }
}

__global__ void __launch_bounds__(512, 1) mlp_mma(
    const float* __restrict__ b1, const float* __restrict__ b2, int l,
    int write_agg)
{
    extern __shared__ __align__(16) char S[];
    char* pAhi = S;                       // 256 x SA bf16
    char* pAlo = S + ATILE_B;
    char* pWh  = S + 2 * ATILE_B;         // staged W1 then W2 (hi)
    char* pWl  = S + 2 * ATILE_B + WTILE_B;
    uint32_t aAhi = smem_u32(pAhi);
    uint32_t aAlo = aAhi + ATILE_B;
    uint32_t aWh  = aAhi + 2 * ATILE_B;
    uint32_t aWl  = aWh + WTILE_B;

    int tid = threadIdx.x, warp = tid >> 5, lane = tid & 31;
    int node0 = blockIdx.x * NODES_PB;

    // ---- load A (x+agg), split hi/lo: 256 rows ----
    const float4* agg4 = (const float4*)g_agg;
#pragma unroll 4
    for (int it = 0; it < 16; it++) {
        int idx = tid + it * 512;
        int row = idx >> 5, k4 = idx & 31;
        int gr = node0 + row;
        float4 v = make_float4(0.f, 0.f, 0.f, 0.f);
        if (gr < N_NODES) v = agg4[(size_t)gr * 32 + k4];
        __nv_bfloat16 h0 = __float2bfloat16(v.x), h1 = __float2bfloat16(v.y);
        __nv_bfloat16 h2 = __float2bfloat16(v.z), h3 = __float2bfloat16(v.w);
        __nv_bfloat16 l0 = __float2bfloat16(v.x - __bfloat162float(h0));
        __nv_bfloat16 l1 = __float2bfloat16(v.y - __bfloat162float(h1));
        __nv_bfloat16 l2 = __float2bfloat16(v.z - __bfloat162float(h2));
        __nv_bfloat16 l3 = __float2bfloat16(v.w - __bfloat162float(h3));
        size_t off = ((size_t)row * SA + k4 * 4) * 2;
        *(uint2*)(pAhi + off) = make_uint2(pk(h0, h1), pk(h2, h3));
        *(uint2*)(pAlo + off) = make_uint2(pk(l0, l1), pk(l2, l3));
    }

    const size_t istr = (size_t)HID * SA;              // elems per image
    const size_t lstr = (size_t)2 * LAYERS * HID * SA; // hi->lo offset
    // ---- stage W1 (hi/lo) ----
    {
        const float4* sh = (const float4*)(g_wt + (size_t)l * istr);
        const float4* sl = (const float4*)(g_wt + lstr + (size_t)l * istr);
        float4* dh = (float4*)pWh; float4* dl = (float4*)pWl;
        for (int i = tid; i < WTILE_B / 16; i += 512) { dh[i] = sh[i]; dl[i] = sl[i]; }
    }
    __syncthreads();

    // warp tiling: 16 warps -> (8 m) x (2 n); warp tile 32x64
    int m0 = (warp >> 1) * 32;
    int n0 = (warp & 1) * 64;
    int g = lane >> 3;
    int arow_off = (lane & 7) + ((g & 1) << 3);
    int akoff    = (g >> 1) << 3;
    int brow_off = (lane & 7) + ((g >> 1) << 3);
    int bkoff    = (g & 1) << 3;

    float acc[2][8][4];
#pragma unroll
    for (int s = 0; s < 2; s++)
#pragma unroll
        for (int j = 0; j < 8; j++)
#pragma unroll
            for (int c = 0; c < 4; c++) acc[s][j][c] = 0.f;

    // ---- GEMM 1 ----
    gemm_warp(aAhi, aAlo, aWh, aWl, m0, n0, arow_off, akoff, brow_off, bkoff, acc);
    __syncthreads();   // all warps done reading A (epilogue overwrites it) and W1

    // ---- epilogue 1: h = relu(acc + b1), split hi/lo back into A tiles ----
    {
        int r0 = m0 + (lane >> 2);
#pragma unroll
        for (int j = 0; j < 8; j++) {
            int col = n0 + j * 8 + (lane & 3) * 2;
            float bj0 = __ldg(b1 + col), bj1 = __ldg(b1 + col + 1);
#pragma unroll
            for (int s = 0; s < 2; s++) {
                int rA = r0 + s * 16, rB = rA + 8;
                float v0 = fmaxf(acc[s][j][0] + bj0, 0.f);
                float v1 = fmaxf(acc[s][j][1] + bj1, 0.f);
                float v2 = fmaxf(acc[s][j][2] + bj0, 0.f);
                float v3 = fmaxf(acc[s][j][3] + bj1, 0.f);
                __nv_bfloat16 h0 = __float2bfloat16(v0), h1 = __float2bfloat16(v1);
                __nv_bfloat16 h2 = __float2bfloat16(v2), h3 = __float2bfloat16(v3);
                __nv_bfloat16 q0 = __float2bfloat16(v0 - __bfloat162float(h0));
                __nv_bfloat16 q1 = __float2bfloat16(v1 - __bfloat162float(h1));
                __nv_bfloat16 q2 = __float2bfloat16(v2 - __bfloat162float(h2));
                __nv_bfloat16 q3 = __float2bfloat16(v3 - __bfloat162float(h3));
                size_t oA = ((size_t)rA * SA + col) * 2;
                size_t oB = ((size_t)rB * SA + col) * 2;
                *(uint32_t*)(pAhi + oA) = pk(h0, h1);
                *(uint32_t*)(pAlo + oA) = pk(q0, q1);
                *(uint32_t*)(pAhi + oB) = pk(h2, h3);
                *(uint32_t*)(pAlo + oB) = pk(q2, q3);
            }
        }
    }
    // ---- stage W2 over W1 (same phase: disjoint smem from H writes) ----
    {
        const float4* sh = (const float4*)(g_wt + (size_t)(LAYERS + l) * istr);
        const float4* sl = (const float4*)(g_wt + lstr + (size_t)(LAYERS + l) * istr);
        float4* dh = (float4*)pWh; float4* dl = (float4*)pWl;
        for (int i = tid; i < WTILE_B / 16; i += 512) { dh[i] = sh[i]; dl[i] = sl[i]; }
    }
    __syncthreads();

#pragma unroll
    for (int s = 0; s < 2; s++)
#pragma unroll
        for (int j = 0; j < 8; j++)
#pragma unroll
            for (int c = 0; c < 4; c++) acc[s][j][c] = 0.f;

    // ---- GEMM 2 ----
    gemm_warp(aAhi, aAlo, aWh, aWl, m0, n0, arow_off, akoff, brow_off, bkoff, acc);
    __syncthreads();   // stage reuses A region

    // ---- epilogue 2: relu(acc + b2) -> fp32 stage (reuses A region) ----
    float* stage = (float*)S;    // 256 x 132 fp32 = 135168 B <= 2*ATILE_B
    {
        int r0 = m0 + (lane >> 2);
#pragma unroll
        for (int j = 0; j < 8; j++) {
            int col = n0 + j * 8 + (lane & 3) * 2;
            float bj0 = __ldg(b2 + col), bj1 = __ldg(b2 + col + 1);
#pragma unroll
            for (int s = 0; s < 2; s++) {
                int rA = r0 + s * 16, rB = rA + 8;
                stage[rA * 132 + col]     = fmaxf(acc[s][j][0] + bj0, 0.f);
                stage[rA * 132 + col + 1] = fmaxf(acc[s][j][1] + bj1, 0.f);
                stage[rB * 132 + col]     = fmaxf(acc[s][j][2] + bj0, 0.f);
                stage[rB * 132 + col + 1] = fmaxf(acc[s][j][3] + bj1, 0.f);
            }
        }
    }
    __syncthreads();

    // ---- coalesced writeback ----
    float4* x4 = (float4*)g_x;
    float4* a4 = (float4*)g_agg;
#pragma unroll 4
    for (int it = 0; it < 16; it++) {
        int idx = tid + it * 512;
        int row = idx >> 5, k4 = idx & 31;
        int gr = node0 + row;
        if (gr < N_NODES) {
            float4 v = *(float4*)&stage[row * 132 + k4 * 4];
            x4[(size_t)gr * 32 + k4] = v;
            if (write_agg) a4[(size_t)gr * 32 + k4] = v;
        }
    }
}

// ---------------------------------------------------------------------------
// Global mean pool (batch sorted -> binary-search ranges)
// ---------------------------------------------------------------------------
__global__ void pool_kernel(const int* __restrict__ batch,
                            float* __restrict__ out) {
    int g = blockIdx.x;
    __shared__ int s_range[2];
    if (threadIdx.x == 0) {
        int lo = 0, hi = N_NODES;
        while (lo < hi) { int m = (lo + hi) >> 1; if (batch[m] < g) lo = m + 1; else hi = m; }
        s_range[0] = lo;
        lo = 0; hi = N_NODES;
        while (lo < hi) { int m = (lo + hi) >> 1; if (batch[m] < g + 1) lo = m + 1; else hi = m; }
        s_range[1] = lo;
    }
    __syncthreads();
    int start = s_range[0], end = s_range[1];
    float sum = 0.f;
    for (int n = start; n < end; n++)
        sum += g_x[(size_t)n * HID + threadIdx.x];
    float cnt = (float)(end - start);
    out[g * HID + threadIdx.x] = sum / fmaxf(cnt, 1.0f);
}

// ---------------------------------------------------------------------------
// Inputs: x_tokens, edge_index, batch, emb, W1, b1, W2, b2
// ---------------------------------------------------------------------------
extern "C" void kernel_launch(void* const* d_in, const int* in_sizes, int n_in,
                              void* d_out, int out_size) {
    const int*   tok   = (const int*)  d_in[0];
    const int*   ei    = (const int*)  d_in[1];
    const int*   batch = (const int*)  d_in[2];
    const float* emb   = (const float*)d_in[3];
    const float* W1    = (const float*)d_in[4];
    const float* b1    = (const float*)d_in[5];
    const float* W2    = (const float*)d_in[6];
    const float* b2    = (const float*)d_in[7];
    float* out = (float*)d_out;

    cudaFuncSetAttribute(mlp_mma, cudaFuncAttributeMaxDynamicSharedMemorySize,
                         SMEM_BYTES);

    prep_w<<<(2 * LAYERS * HID * HID + 255) / 256, 256>>>(W1, W2);
    embed_kernel<<<(N_NODES * 32 + 255) / 256, 256>>>(tok, emb);

    for (int l = 0; l < LAYERS; l++) {
        scatter_kernel<<<(N_EDGES * 32 + 255) / 256, 256>>>(ei);
        mlp_mma<<<(N_NODES + NODES_PB - 1) / NODES_PB, 512, SMEM_BYTES>>>(
            b1 + (size_t)l * HID, b2 + (size_t)l * HID, l,
            (l < LAYERS - 1) ? 1 : 0);
    }

    pool_kernel<<<N_GRAPHS, HID>>>(batch, out);
}